// round 3
// baseline (speedup 1.0000x reference)
#include <cuda_runtime.h>

#define GRID  152
#define NT    256
#define NBMAX 7
#define SEQ   512
#define HID   64

typedef unsigned long long u64t;

// Packed dual-FMA: {d.lo,d.hi} = {a.lo*b.lo+c.lo, a.hi*b.hi+c.hi}
#define FMA2(d, a, b, c) \
    asm("fma.rn.f32x2 %0, %1, %2, %3;" : "=l"(d) : "l"(a), "l"(b), "l"(c))

__device__ __forceinline__ u64t pack2(float lo, float hi) {
    u64t v;
    asm("mov.b64 %0, {%1, %2};" : "=l"(v) : "r"(__float_as_uint(lo)), "r"(__float_as_uint(hi)));
    return v;
}
__device__ __forceinline__ float pair_sum(u64t v) {
    unsigned lo, hi;
    asm("mov.b64 {%0, %1}, %2;" : "=r"(lo), "=r"(hi) : "l"(v));
    return __uint_as_float(lo) + __uint_as_float(hi);
}

__device__ __forceinline__ float sigf(float x) {
    return __fdividef(1.0f, 1.0f + __expf(-x));
}
__device__ __forceinline__ float tanh_f(float x) {
    return __fdividef(2.0f, 1.0f + __expf(-2.0f * x)) - 1.0f;
}

__global__ __launch_bounds__(NT, 1)
void lstm_kernel(const float* __restrict__ input,
                 const float* __restrict__ Wih1, const float* __restrict__ Whh1,
                 const float* __restrict__ bih1, const float* __restrict__ bhh1,
                 const float* __restrict__ Wih2, const float* __restrict__ Whh2,
                 const float* __restrict__ bih2, const float* __restrict__ bhh2,
                 const float* __restrict__ Wlin, const float* __restrict__ blin,
                 float* __restrict__ out)
{
    __shared__ __align__(16) float x_s[NBMAX * SEQ];
    __shared__ __align__(16) float h1s[NBMAX][HID], c1s[NBMAX][HID];
    __shared__ __align__(16) float h2s[NBMAX][HID], c2s[NBMAX][HID];
    __shared__ __align__(16) float g1s[NBMAX][256];
    __shared__ __align__(16) float g2s[NBMAX][256];
    __shared__ float wlin_s[HID];
    __shared__ float blin_s;

    const int j   = threadIdx.x;          // gate column 0..255 (i,f,g,o blocks of 64)
    const int bid = blockIdx.x;
    const int b0  = (bid * 1024) / GRID;
    const int b1  = ((bid + 1) * 1024) / GRID;
    const int nb  = b1 - b0;              // 6 or 7 batch rows per block

    // ---- weight columns into packed-b64 registers (2 k-values per reg) ----
    // Row j of each (256,64) matrix is contiguous: natural even/odd-k packing.
    u64t w1[HID / 2], wa[HID / 2], wb[HID / 2];
    {
        const ulonglong2* p1 = (const ulonglong2*)(Whh1 + j * HID);
        const ulonglong2* pa = (const ulonglong2*)(Wih2 + j * HID);
        const ulonglong2* pb = (const ulonglong2*)(Whh2 + j * HID);
        #pragma unroll
        for (int k = 0; k < 16; k++) {
            ulonglong2 v;
            v = p1[k]; w1[2*k] = v.x; w1[2*k+1] = v.y;
            v = pa[k]; wa[2*k] = v.x; wa[2*k+1] = v.y;
            v = pb[k]; wb[2*k] = v.x; wb[2*k+1] = v.y;
        }
    }
    const float wx    = Wih1[j];               // (4H,1) input weight, x is scalar
    const float bias1 = bih1[j] + bhh1[j];
    const float bias2 = bih2[j] + bhh2[j];
    const u64t  bias1p = pack2(bias1, 0.0f);   // folded into accumulator init
    const u64t  bias2p = pack2(bias2, 0.0f);
    if (j < HID) wlin_s[j] = Wlin[j];
    if (j == 0)  blin_s = blin[0];

    // ---- stage this block's x rows into smem; zero states ----
    for (int idx = j; idx < nb * SEQ; idx += NT)
        x_s[idx] = input[(b0 + (idx >> 9)) * SEQ + (idx & (SEQ - 1))];
    for (int idx = j; idx < nb * HID; idx += NT) {
        int bb = idx >> 6, u = idx & 63;
        h1s[bb][u] = 0.f; c1s[bb][u] = 0.f; h2s[bb][u] = 0.f; c2s[bb][u] = 0.f;
    }
    __syncthreads();

    for (int t = 0; t < SEQ; t++) {
        // ---- Phase 0: layer-1 gates: g1 = Whh1[j,:].h1 + wx*x + bias1 ----
        for (int b = 0; b < nb; b++) {
            const ulonglong2* hp = (const ulonglong2*)h1s[b];  // broadcast LDS.128
            u64t a0 = bias1p, a1 = 0ull;
            #pragma unroll
            for (int k = 0; k < 16; k++) {
                ulonglong2 h = hp[k];
                FMA2(a0, w1[2*k],   h.x, a0);
                FMA2(a1, w1[2*k+1], h.y, a1);
            }
            g1s[b][j] = pair_sum(a0) + pair_sum(a1) + wx * x_s[b * SEQ + t];
        }
        __syncthreads();

        // ---- Phase 1: layer-1 state update ----
        for (int task = j; task < nb * HID; task += NT) {
            int bb = task >> 6, u = task & 63;
            float gi = g1s[bb][u], gf = g1s[bb][u + 64];
            float gg = g1s[bb][u + 128], go = g1s[bb][u + 192];
            float c = sigf(gf) * c1s[bb][u] + sigf(gi) * tanh_f(gg);
            c1s[bb][u] = c;
            h1s[bb][u] = sigf(go) * tanh_f(c);
        }
        __syncthreads();

        // ---- Phase 2: layer-2 gates: g2 = Wih2[j,:].h1 + Whh2[j,:].h2 + bias2 ----
        for (int b = 0; b < nb; b++) {
            const ulonglong2* hp1 = (const ulonglong2*)h1s[b];
            const ulonglong2* hp2 = (const ulonglong2*)h2s[b];
            u64t a0 = bias2p, a1 = 0ull, d0 = 0ull, d1 = 0ull;
            #pragma unroll
            for (int k = 0; k < 16; k++) {
                ulonglong2 h = hp1[k];
                FMA2(a0, wa[2*k],   h.x, a0);
                FMA2(a1, wa[2*k+1], h.y, a1);
            }
            #pragma unroll
            for (int k = 0; k < 16; k++) {
                ulonglong2 h = hp2[k];
                FMA2(d0, wb[2*k],   h.x, d0);
                FMA2(d1, wb[2*k+1], h.y, d1);
            }
            g2s[b][j] = (pair_sum(a0) + pair_sum(a1))
                      + (pair_sum(d0) + pair_sum(d1));
        }
        __syncthreads();

        // ---- Phase 3: layer-2 state update ----
        for (int task = j; task < nb * HID; task += NT) {
            int bb = task >> 6, u = task & 63;
            float gi = g2s[bb][u], gf = g2s[bb][u + 64];
            float gg = g2s[bb][u + 128], go = g2s[bb][u + 192];
            float c = sigf(gf) * c2s[bb][u] + sigf(gi) * tanh_f(gg);
            c2s[bb][u] = c;
            h2s[bb][u] = sigf(go) * tanh_f(c);
        }
        __syncthreads();

        // ---- Phase 4: output projection (warp b reduces h2[b] . Wlin) ----
        // Safe without an extra barrier: next write to h2s is Phase 3 of the
        // next iteration, separated by 3 barriers.
        int w = j >> 5, lane = j & 31;
        if (w < nb) {
            float v = h2s[w][lane]      * wlin_s[lane]
                    + h2s[w][lane + 32] * wlin_s[lane + 32];
            #pragma unroll
            for (int off = 16; off > 0; off >>= 1)
                v += __shfl_xor_sync(0xffffffffu, v, off);
            if (lane == 0) out[(b0 + w) * SEQ + t] = v + blin_s;
        }
    }
}

extern "C" void kernel_launch(void* const* d_in, const int* in_sizes, int n_in,
                              void* d_out, int out_size)
{
    const float* input = (const float*)d_in[0];
    const float* Wih1  = (const float*)d_in[1];
    const float* Whh1  = (const float*)d_in[2];
    const float* bih1  = (const float*)d_in[3];
    const float* bhh1  = (const float*)d_in[4];
    const float* Wih2  = (const float*)d_in[5];
    const float* Whh2  = (const float*)d_in[6];
    const float* bih2  = (const float*)d_in[7];
    const float* bhh2  = (const float*)d_in[8];
    const float* Wlin  = (const float*)d_in[9];
    const float* blin  = (const float*)d_in[10];
    // d_in[11] = future_preds (static 0) — intentionally unused.
    float* out = (float*)d_out;

    lstm_kernel<<<GRID, NT>>>(input, Wih1, Whh1, bih1, bhh1,
                              Wih2, Whh2, bih2, bhh2, Wlin, blin, out);
}

// round 9
// speedup vs baseline: 1.0152x; 1.0152x over previous
#include <cuda_runtime.h>

#define GRID  152
#define NT    512
#define NBMAX 7
#define SEQ   512
#define HID   64
#define HROW  72   // padded h-row: halves at float offsets 0 and 36 (bank-shifted)

typedef unsigned long long u64t;

// Packed dual-FMA: {d.lo,d.hi} = {a.lo*b.lo+c.lo, a.hi*b.hi+c.hi}
#define FMA2(d, a, b, c) \
    asm("fma.rn.f32x2 %0, %1, %2, %3;" : "=l"(d) : "l"(a), "l"(b), "l"(c))

__device__ __forceinline__ u64t pack2(float lo, float hi) {
    u64t v;
    asm("mov.b64 %0, {%1, %2};" : "=l"(v) : "r"(__float_as_uint(lo)), "r"(__float_as_uint(hi)));
    return v;
}
__device__ __forceinline__ float pair_sum(u64t v) {
    unsigned lo, hi;
    asm("mov.b64 {%0, %1}, %2;" : "=r"(lo), "=r"(hi) : "l"(v));
    return __uint_as_float(lo) + __uint_as_float(hi);
}

__device__ __forceinline__ float sigf(float x) {
    return __fdividef(1.0f, 1.0f + __expf(-x));
}
__device__ __forceinline__ float tanh_f(float x) {
    return __fdividef(2.0f, 1.0f + __expf(-2.0f * x)) - 1.0f;
}

// logical hidden index u (0..63) -> padded physical float offset
__device__ __forceinline__ int physu(int u) { return u + ((u >> 5) << 2); }

struct Smem {
    float x_s[NBMAX * SEQ];
    float h1s[NBMAX][HROW];              // padded (halves bank-shifted)
    float h2s[NBMAX][HROW];
    float c1s[NBMAX][HID], c2s[NBMAX][HID];
    float g1s[NBMAX][256];
    float g2s[NBMAX][256];
    float wlin_s[HID];
    float blin_s;
};

// Core time loop. NB compile-time so every b-loop fully unrolls.
// Thread pair (2j, 2j+1) owns gate j; `half` selects k-range [32*half, 32*half+32).
// Minimal accumulator chains (1 in P0, 2 in P2): 4 warps/SMSP supply the
// cross-warp ILP the FMA pipe needs (lat/rt = 2 chains), keeping regs <= ~120.
template<int NB>
__device__ __forceinline__ void lstm_core(
    Smem* s, int tid, int j, int half, int b0,
    const u64t* w1, const u64t* wa, const u64t* wb,
    float wx, u64t bias1p, u64t bias2p,
    float* __restrict__ out)
{
    const int hoff = half * 36;          // float offset of this thread's h-half

    for (int t = 0; t < SEQ; t++) {
        // ---- Phase 0: layer-1 gates: partial dot over 32 k's, combine via shfl ----
        #pragma unroll
        for (int b = 0; b < NB; b++) {
            const ulonglong2* hp = (const ulonglong2*)&s->h1s[b][hoff];  // 16B-aligned
            u64t a0 = bias1p;                      // bias folded into half-0 only
            #pragma unroll
            for (int k = 0; k < 8; k++) {
                ulonglong2 h = hp[k];
                FMA2(a0, w1[2*k],   h.x, a0);
                FMA2(a0, w1[2*k+1], h.y, a0);
            }
            float v = pair_sum(a0);
            v += __shfl_xor_sync(0xffffffffu, v, 1);      // combine partner halves
            if (half == 0)
                s->g1s[b][j] = v + wx * s->x_s[b * SEQ + t];
        }
        __syncthreads();

        // ---- Phase 1: layer-1 state update (one task per thread) ----
        if (tid < NB * HID) {
            int bb = tid >> 6, u = tid & 63;
            float gi = s->g1s[bb][u],       gf = s->g1s[bb][u + 64];
            float gg = s->g1s[bb][u + 128], go = s->g1s[bb][u + 192];
            float c = sigf(gf) * s->c1s[bb][u] + sigf(gi) * tanh_f(gg);
            s->c1s[bb][u] = c;
            s->h1s[bb][physu(u)] = sigf(go) * tanh_f(c);
        }
        __syncthreads();

        // ---- Phase 2: layer-2 gates: two partial dots (h1, h2), 2 chains ----
        #pragma unroll
        for (int b = 0; b < NB; b++) {
            const ulonglong2* hp1 = (const ulonglong2*)&s->h1s[b][hoff];
            const ulonglong2* hp2 = (const ulonglong2*)&s->h2s[b][hoff];
            u64t a0 = bias2p, d0 = 0ull;
            #pragma unroll
            for (int k = 0; k < 8; k++) {
                ulonglong2 h1v = hp1[k];
                ulonglong2 h2v = hp2[k];
                FMA2(a0, wa[2*k],   h1v.x, a0);
                FMA2(a0, wa[2*k+1], h1v.y, a0);
                FMA2(d0, wb[2*k],   h2v.x, d0);
                FMA2(d0, wb[2*k+1], h2v.y, d0);
            }
            float v = pair_sum(a0) + pair_sum(d0);
            v += __shfl_xor_sync(0xffffffffu, v, 1);
            if (half == 0)
                s->g2s[b][j] = v;
        }
        __syncthreads();

        // ---- Phase 3: layer-2 state update ----
        if (tid < NB * HID) {
            int bb = tid >> 6, u = tid & 63;
            float gi = s->g2s[bb][u],       gf = s->g2s[bb][u + 64];
            float gg = s->g2s[bb][u + 128], go = s->g2s[bb][u + 192];
            float c = sigf(gf) * s->c2s[bb][u] + sigf(gi) * tanh_f(gg);
            s->c2s[bb][u] = c;
            s->h2s[bb][physu(u)] = sigf(go) * tanh_f(c);
        }
        __syncthreads();

        // ---- Phase 4: output projection (warp w reduces h2[w] . Wlin) ----
        // Reads h2s AFTER the phase-3 barrier; next h2s write is 3 barriers away.
        int w = tid >> 5, lane = tid & 31;
        if (w < NB) {
            float v = s->h2s[w][lane]      * s->wlin_s[lane]        // physu(lane)=lane
                    + s->h2s[w][lane + 36] * s->wlin_s[lane + 32];  // physu(lane+32)
            #pragma unroll
            for (int off = 16; off > 0; off >>= 1)
                v += __shfl_xor_sync(0xffffffffu, v, off);
            if (lane == 0) out[(b0 + w) * SEQ + t] = v + s->blin_s;
        }
    }
}

__global__ __launch_bounds__(NT, 1)
void lstm_kernel(const float* __restrict__ input,
                 const float* __restrict__ Wih1, const float* __restrict__ Whh1,
                 const float* __restrict__ bih1, const float* __restrict__ bhh1,
                 const float* __restrict__ Wih2, const float* __restrict__ Whh2,
                 const float* __restrict__ bih2, const float* __restrict__ bhh2,
                 const float* __restrict__ Wlin, const float* __restrict__ blin,
                 float* __restrict__ out)
{
    __shared__ __align__(16) Smem s;

    const int tid  = threadIdx.x;
    const int j    = tid >> 1;           // gate column 0..255
    const int half = tid & 1;            // k-half: [0,32) or [32,64)
    const int bid  = blockIdx.x;
    const int b0   = (bid * 1024) / GRID;
    const int b1   = ((bid + 1) * 1024) / GRID;
    const int nb   = b1 - b0;            // 6 or 7 batch rows per block

    // ---- this thread's 32 weight k-values per matrix, packed b64 (96 regs) ----
    u64t w1[16], wa[16], wb[16];
    {
        const ulonglong2* p1 = (const ulonglong2*)(Whh1 + j * HID + half * 32);
        const ulonglong2* pa = (const ulonglong2*)(Wih2 + j * HID + half * 32);
        const ulonglong2* pb = (const ulonglong2*)(Whh2 + j * HID + half * 32);
        #pragma unroll
        for (int k = 0; k < 8; k++) {
            ulonglong2 v;
            v = p1[k]; w1[2*k] = v.x; w1[2*k+1] = v.y;
            v = pa[k]; wa[2*k] = v.x; wa[2*k+1] = v.y;
            v = pb[k]; wb[2*k] = v.x; wb[2*k+1] = v.y;
        }
    }
    const float wx     = Wih1[j];        // (4H,1) input weight, x is scalar
    // biases folded into the half-0 accumulator init only
    const u64t  bias1p = (half == 0) ? pack2(bih1[j] + bhh1[j], 0.0f) : 0ull;
    const u64t  bias2p = (half == 0) ? pack2(bih2[j] + bhh2[j], 0.0f) : 0ull;
    if (tid < HID) s.wlin_s[tid] = Wlin[tid];
    if (tid == 0)  s.blin_s = blin[0];

    // ---- stage x rows; zero states (including h padding) ----
    for (int idx = tid; idx < nb * SEQ; idx += NT)
        s.x_s[idx] = input[(b0 + (idx >> 9)) * SEQ + (idx & (SEQ - 1))];
    for (int idx = tid; idx < NBMAX * HROW; idx += NT) {
        int bb = idx / HROW, u = idx % HROW;
        s.h1s[bb][u] = 0.f; s.h2s[bb][u] = 0.f;
    }
    for (int idx = tid; idx < NBMAX * HID; idx += NT) {
        int bb = idx >> 6, u = idx & 63;
        s.c1s[bb][u] = 0.f; s.c2s[bb][u] = 0.f;
    }
    __syncthreads();

    if (nb == 7)
        lstm_core<7>(&s, tid, j, half, b0, w1, wa, wb, wx, bias1p, bias2p, out);
    else
        lstm_core<6>(&s, tid, j, half, b0, w1, wa, wb, wx, bias1p, bias2p, out);
}

extern "C" void kernel_launch(void* const* d_in, const int* in_sizes, int n_in,
                              void* d_out, int out_size)
{
    const float* input = (const float*)d_in[0];
    const float* Wih1  = (const float*)d_in[1];
    const float* Whh1  = (const float*)d_in[2];
    const float* bih1  = (const float*)d_in[3];
    const float* bhh1  = (const float*)d_in[4];
    const float* Wih2  = (const float*)d_in[5];
    const float* Whh2  = (const float*)d_in[6];
    const float* bih2  = (const float*)d_in[7];
    const float* bhh2  = (const float*)d_in[8];
    const float* Wlin  = (const float*)d_in[9];
    const float* blin  = (const float*)d_in[10];
    // d_in[11] = future_preds (static 0) — intentionally unused.
    float* out = (float*)d_out;

    lstm_kernel<<<GRID, NT>>>(input, Wih1, Whh1, bih1, bhh1,
                              Wih2, Whh2, bih2, bhh2, Wlin, blin, out);
}